// round 8
// baseline (speedup 1.0000x reference)
#include <cuda_runtime.h>

namespace {
constexpr int H = 64, W = 64;
constexpr int C = 384;   // 48 positions * 8 channels
constexpr int B = 32;
constexpr int PLANES = B * C;          // 12288
}

// 5-tap normalized gaussian from fractional offset sub, sigma=0.5.
// e_j ∝ exp(-2(j-2)^2) * t^(j-2), t = exp(-4*sub); common factor exp(-2sub^2)
// cancels in normalization. Max rel err vs expf-loop ~1e-6 (<< 1e-3 tol).
__device__ __forceinline__ void gauss5(float sub, float w[5]) {
  const float c1 = 0.135335283236612692f;    // exp(-2)
  const float c2 = 3.35462627902511839e-4f;  // exp(-8)
  float t  = __expf(-4.0f * sub);
  float it = 1.0f / t;
  float e0 = c2 * it * it;
  float e1 = c1 * it;
  float e2 = 1.0f;
  float e3 = c1 * t;
  float e4 = c2 * t * t;
  float inv = 1.0f / (e0 + e1 + e2 + e3 + e4);
  w[0] = e0 * inv; w[1] = e1 * inv; w[2] = e2 * inv;
  w[3] = e3 * inv; w[4] = e4 * inv;
}

__global__ __launch_bounds__(128) void displace_gauss_kernel(
    const float* __restrict__ x, const float* __restrict__ offset,
    float* __restrict__ out) {
  const int tid  = threadIdx.x;
  const int gw   = (blockIdx.x * 128 + tid) >> 5;  // global warp id
  const int lane = tid & 31;
  const int pp   = gw >> 3;            // plane pair index
  const int yb   = gw & 7;             // y-band 0..7
  const int y0   = yb * 8;
  const int half = lane >> 4;          // which plane of the pair
  const int lg   = lane & 15;          // col group within plane
  const int x0   = lg * 4;
  const int plane = pp * 2 + half;
  const int p = (plane % C) >> 3;      // pair shares position group

  const float ox = __ldg(&offset[2 * p + 0]);
  const float oy = __ldg(&offset[2 * p + 1]);
  const float rxv = rintf(ox), ryv = rintf(oy);   // matches jnp.round
  const int dx = (int)rxv, dy = (int)ryv;

  float* __restrict__ dst = out + (size_t)plane * (H * W) + y0 * W + x0;

  // warp-uniform y-liveness (conservative: pad-tightening only shrinks live set)
  if ((y0 + 9 - dy < 0) || (y0 - 2 - dy > H - 1)) {
    const float4 z = make_float4(0.f, 0.f, 0.f, 0.f);
#pragma unroll
    for (int o = 0; o < 8; o++)
      __stcs(reinterpret_cast<float4*>(dst + o * W), z);
    return;
  }

  float wx[5], wy[5];
  gauss5(ox - rxv, wx);
  gauss5(oy - ryv, wy);

  const float* __restrict__ src = x + (size_t)plane * (H * W);

  float acc[8][4];
#pragma unroll
  for (int o = 0; o < 8; o++)
#pragma unroll
    for (int u = 0; u < 4; u++) acc[o][u] = 0.f;

  if ((dx & 3) == 0) {
    // aligned path (always for this problem's offsets): three quads per row.
    // Quad validity = (displaced cols inside image: conv padding) AND
    // (source cols inside image: displacement fill). Quads are 4-aligned and
    // both region edges are multiples of 4, so validity is all-or-none.
    const int sxv = x0 - dx;           // source col of q1, multiple of 4
    const int b0 = sxv - 4, b2 = sxv + 4;
    // q0 disp cols x0-4..x0-1: inside image iff lg>0 (conv padding at lg==0)
    const bool ok0 = (lg != 0)  && ((unsigned)b0  <= (unsigned)(W - 4));
    const bool ok1 =               ((unsigned)sxv <= (unsigned)(W - 4));
    // q2 disp cols x0+4..x0+7: inside image iff lg<15
    const bool ok2 = (lg != 15) && ((unsigned)b2  <= (unsigned)(W - 4));
#pragma unroll
    for (int r = 0; r < 12; r++) {
      const int pr = y0 - 2 + r;       // displaced (conv tap) row
      // tap must be zero if pr outside image (conv padding) OR source invalid
      const bool syok = ((unsigned)pr < (unsigned)H) &&
                        ((unsigned)(pr - dy) < (unsigned)H);
      const float* rowp = src + (pr - dy) * W;
      float4 q0 = make_float4(0.f, 0.f, 0.f, 0.f);
      float4 q1 = make_float4(0.f, 0.f, 0.f, 0.f);
      float4 q2 = make_float4(0.f, 0.f, 0.f, 0.f);
      if (syok && ok0) q0 = *reinterpret_cast<const float4*>(rowp + b0);
      if (syok && ok1) q1 = *reinterpret_cast<const float4*>(rowp + sxv);
      if (syok && ok2) q2 = *reinterpret_cast<const float4*>(rowp + b2);
      // disp cols: q0.z=x0-2, q0.w=x0-1, q1=x0..x0+3, q2.x=x0+4, q2.y=x0+5
      float h0 = wx[0]*q0.z + wx[1]*q0.w + wx[2]*q1.x + wx[3]*q1.y + wx[4]*q1.z;
      float h1 = wx[0]*q0.w + wx[1]*q1.x + wx[2]*q1.y + wx[3]*q1.z + wx[4]*q1.w;
      float h2 = wx[0]*q1.x + wx[1]*q1.y + wx[2]*q1.z + wx[3]*q1.w + wx[4]*q2.x;
      float h3 = wx[0]*q1.y + wx[1]*q1.z + wx[2]*q1.w + wx[3]*q2.x + wx[4]*q2.y;
#pragma unroll
      for (int o = 0; o < 8; o++) {
        int i = r - o;                 // compile-time pruned
        if (i >= 0 && i < 5) {
          float wv = wy[i];
          acc[o][0] += wv * h0; acc[o][1] += wv * h1;
          acc[o][2] += wv * h2; acc[o][3] += wv * h3;
        }
      }
    }
  } else {
    // generic scalar fallback (not taken for this problem's offset grid)
#pragma unroll
    for (int r = 0; r < 12; r++) {
      const int pr = y0 - 2 + r;
      const bool syok = ((unsigned)pr < (unsigned)H) &&
                        ((unsigned)(pr - dy) < (unsigned)H);
      const float* rowp = src + (pr - dy) * W;
      float v[8];
#pragma unroll
      for (int u = 0; u < 8; u++) {    // displaced cols x0-2 .. x0+5
        const int pc = x0 - 2 + u;
        v[u] = 0.f;
        if (syok && (unsigned)pc < (unsigned)W &&
            (unsigned)(pc - dx) < (unsigned)W)
          v[u] = rowp[pc - dx];
      }
      float h[4];
#pragma unroll
      for (int u = 0; u < 4; u++)
        h[u] = wx[0]*v[u] + wx[1]*v[u+1] + wx[2]*v[u+2]
             + wx[3]*v[u+3] + wx[4]*v[u+4];
#pragma unroll
      for (int o = 0; o < 8; o++) {
        int i = r - o;
        if (i >= 0 && i < 5) {
          float wv = wy[i];
#pragma unroll
          for (int u = 0; u < 4; u++) acc[o][u] += wv * h[u];
        }
      }
    }
  }

#pragma unroll
  for (int o = 0; o < 8; o++) {
    float4 v = make_float4(acc[o][0], acc[o][1], acc[o][2], acc[o][3]);
    __stcs(reinterpret_cast<float4*>(dst + o * W), v);
  }
}

extern "C" void kernel_launch(void* const* d_in, const int* in_sizes, int n_in,
                              void* d_out, int out_size) {
  const float* x = (const float*)d_in[0];
  const float* offset = (const float*)d_in[1];
  float* out = (float*)d_out;
  // warps = (PLANES/2 pairs) * 8 y-bands; 4 warps per 128-thread CTA
  displace_gauss_kernel<<<(PLANES / 2) * 8 / 4, 128>>>(x, offset, out);
}